// round 9
// baseline (speedup 1.0000x reference)
#include <cuda_runtime.h>

#define NCLS 18
#define BLOCKS 1184          // 148 SMs * 8
#define THREADS 256

// Scratch (no device allocation allowed). __device__ globals are zero-init.
__device__ float        g_accum;   // running sum of block partials
__device__ unsigned int g_count;   // block-completion counter

__global__ __launch_bounds__(THREADS)
void ce_fused_kernel(const float* __restrict__ x,
                     const float* __restrict__ l,
                     float* __restrict__ out,
                     int B)
{
    float acc = 0.0f;

    for (int row = blockIdx.x * blockDim.x + threadIdx.x;
         row < B;
         row += gridDim.x * blockDim.x)
    {
        // Row base = row*72 bytes -> 8-byte aligned: float2 loads are legal.
        const float2* __restrict__ xr =
            reinterpret_cast<const float2*>(x + (size_t)row * NCLS);
        const float2* __restrict__ lr =
            reinterpret_cast<const float2*>(l + (size_t)row * NCLS);

        float xs[NCLS], ls[NCLS];
        #pragma unroll
        for (int j = 0; j < NCLS / 2; j++) {
            float2 a = __ldg(xr + j);
            float2 b = __ldg(lr + j);
            xs[2*j]   = a.x; xs[2*j+1] = a.y;
            ls[2*j]   = b.x; ls[2*j+1] = b.y;
        }

        // Max-pass consumes all 9 x-loads at once -> ptxas front-batches all
        // LDGs (empirically the highest-MLP schedule for this loop: R1).
        float m = xs[0];
        #pragma unroll
        for (int c = 1; c < NCLS; c++) m = fmaxf(m, xs[c]);

        float se = 0.0f, suml = 0.0f, dot = 0.0f;
        #pragma unroll
        for (int c = 0; c < NCLS; c++) {
            se   += __expf(xs[c] - m);
            suml += ls[c];
            dot   = fmaf(xs[c], ls[c], dot);
        }
        float lse = m + __logf(se);

        // -sum_c (x_c - lse) * l_c = lse*sum(l) - dot(x,l)
        acc += lse * suml - dot;
    }

    // ---- Block tree reduction
    __shared__ float s[THREADS];
    s[threadIdx.x] = acc;
    __syncthreads();
    #pragma unroll
    for (int o = THREADS / 2; o > 0; o >>= 1) {
        if (threadIdx.x < o) s[threadIdx.x] += s[threadIdx.x + o];
        __syncthreads();
    }

    // ---- One float atomic per block; last block finalizes + re-arms.
    if (threadIdx.x == 0) {
        atomicAdd(&g_accum, s[0]);
        __threadfence();                         // order accum before counter
        unsigned int t = atomicAdd(&g_count, 1u);
        if (t == (unsigned int)(gridDim.x - 1)) {
            float total = g_accum;
            out[0] = total / (float)B;
            g_accum = 0.0f;                      // re-arm for next replay
            __threadfence();
            g_count = 0u;
        }
    }
}

extern "C" void kernel_launch(void* const* d_in, const int* in_sizes, int n_in,
                              void* d_out, int out_size)
{
    const float* x = (const float*)d_in[0];   // output       [B, 18] f32
    const float* l = (const float*)d_in[1];   // labels_soft  [B, 18] f32
    float* out = (float*)d_out;
    int B = in_sizes[0] / NCLS;

    ce_fused_kernel<<<BLOCKS, THREADS>>>(x, l, out, B);
}